// round 5
// baseline (speedup 1.0000x reference)
#include <cuda_runtime.h>
#include <cstdint>
#include <cmath>

// ---------------------------------------------------------------------------
// WeightedRankNet with bucket-sorted gather:
//   1) zero histogram
//   2) col16 partial sums + bucket histogram (fused)
//   3) finalize avg + exclusive bucket scan (1 block)
//   4) scatter (doc, elem) pairs into bucket order
//   5) final: gather table rows in doc-order (DRAM-local), compute, out[elem]
// Threefry-2x32-20, key=(0,1), partitionable: bits = out0 ^ out1.
// ---------------------------------------------------------------------------

#define N_FEAT        136
#define COL_DOCLEN    14
#define COL_WHOLE_LEN 16
#define COL_TF        24
#define COL_INLINK    127
#define COL_OUTLINK   128
#define COL_PAGERANK  129

#define TPB        256
#define SUM_BLOCKS 1024
#define NB         65536          // buckets
#define BSHIFT     4              // 16 rows per bucket
#define SCAN_TPB   1024
#define PER_TH     (NB / SCAN_TPB)  // 64
#define PAIR_CAP   (1 << 20)

__device__ float g_partials[SUM_BLOCKS];
__device__ float g_avg;
__device__ int   g_hist[NB];
__device__ int   g_offsets[NB];
__device__ int2  g_pairs[PAIR_CAP];

// ---- 1) zero histogram -------------------------------------------------------
__global__ void zero_hist_kernel() {
    int i = blockIdx.x * blockDim.x + threadIdx.x;
    if (i < NB) g_hist[i] = 0;
}

// ---- 2) col16 partial sums + histogram ----------------------------------------
__global__ void __launch_bounds__(TPB)
col16_hist_kernel(const float* __restrict__ gf,
                  const int* __restrict__ idxs,
                  int n_docs, int batch)
{
    const int tid      = blockIdx.x * blockDim.x + threadIdx.x;
    const int nthreads = gridDim.x * blockDim.x;

    // histogram of bucket ids (small sequential read + spread atomics)
    for (int i = tid; i < batch; i += nthreads) {
        int d = __ldg(idxs + i);
        atomicAdd(&g_hist[d >> BSHIFT], 1);
    }

    // strided column-16 walk
    float s = 0.0f;
    for (long long i = tid; i < n_docs; i += nthreads)
        s += __ldg(gf + i * N_FEAT + COL_WHOLE_LEN);

    __shared__ float sd[TPB];
    sd[threadIdx.x] = s;
    __syncthreads();
    for (int k = TPB / 2; k > 0; k >>= 1) {
        if (threadIdx.x < k) sd[threadIdx.x] += sd[threadIdx.x + k];
        __syncthreads();
    }
    if (threadIdx.x == 0) g_partials[blockIdx.x] = sd[0];
}

// ---- 3) finalize avg + exclusive bucket scan (one block) ----------------------
__global__ void __launch_bounds__(SCAN_TPB)
finalize_scan_kernel(int n_docs)
{
    const int t = threadIdx.x;

    // (a) fold col16 partials -> g_avg (deterministic fixed order)
    __shared__ float fd[SCAN_TPB];
    fd[t] = (t < SUM_BLOCKS) ? g_partials[t] : 0.0f;
    __syncthreads();
    for (int k = SCAN_TPB / 2; k > 0; k >>= 1) {
        if (t < k) fd[t] += fd[t + k];
        __syncthreads();
    }
    if (t == 0) g_avg = fd[0] / (float)n_docs;

    // (b) exclusive scan of 65536 bucket counts
    int local[PER_TH];
    int lsum = 0;
    #pragma unroll
    for (int j = 0; j < PER_TH; j++) {
        local[j] = g_hist[t * PER_TH + j];
        lsum += local[j];
    }

    __shared__ int ss[SCAN_TPB];
    ss[t] = lsum;
    __syncthreads();
    // inclusive scan over thread sums
    for (int off = 1; off < SCAN_TPB; off <<= 1) {
        int v = (t >= off) ? ss[t - off] : 0;
        __syncthreads();
        ss[t] += v;
        __syncthreads();
    }
    int running = ss[t] - lsum;  // exclusive base for this thread
    #pragma unroll
    for (int j = 0; j < PER_TH; j++) {
        g_offsets[t * PER_TH + j] = running;
        running += local[j];
    }
}

// ---- 4) scatter (doc, elem) pairs into bucket order ----------------------------
__global__ void __launch_bounds__(TPB)
scatter_kernel(const int* __restrict__ idxs, int batch)
{
    const int tid      = blockIdx.x * blockDim.x + threadIdx.x;
    const int nthreads = gridDim.x * blockDim.x;
    for (int i = tid; i < batch; i += nthreads) {
        int d = __ldg(idxs + i);
        int p = atomicAdd(&g_offsets[d >> BSHIFT], 1);
        g_pairs[p] = make_int2(d, i);
    }
}

// ---- Threefry-2x32 -------------------------------------------------------------
__device__ __forceinline__ uint32_t rotl32(uint32_t x, uint32_t r) {
    return __funnelshift_l(x, x, r);
}

__device__ __forceinline__ uint32_t threefry_bits(uint32_t ctr) {
    uint32_t x0 = 0u;
    uint32_t x1 = ctr;
    const uint32_t ks0 = 0u, ks1 = 1u, ks2 = 0x1BD11BDBu;
    x0 += ks0; x1 += ks1;
#define TF_R(r) { x0 += x1; x1 = rotl32(x1, (r)); x1 ^= x0; }
    TF_R(13) TF_R(15) TF_R(26) TF_R(6)
    x0 += ks1; x1 += ks2 + 1u;
    TF_R(17) TF_R(29) TF_R(16) TF_R(24)
    x0 += ks2; x1 += ks0 + 2u;
    TF_R(13) TF_R(15) TF_R(26) TF_R(6)
    x0 += ks0; x1 += ks1 + 3u;
    TF_R(17) TF_R(29) TF_R(16) TF_R(24)
    x0 += ks1; x1 += ks2 + 4u;
    TF_R(13) TF_R(15) TF_R(26) TF_R(6)
    x0 += ks2; x1 += ks0 + 5u;
#undef TF_R
    return x0 ^ x1;
}

// ---- 5) final: locality-ordered gather + compute + scatter out -----------------
__global__ void __launch_bounds__(TPB)
final_kernel(const float* __restrict__ gf,
             const float* __restrict__ s_k1,
             const float* __restrict__ s_b,
             const float* __restrict__ s_bw,
             const float* __restrict__ s_pr,
             const float* __restrict__ s_in,
             const float* __restrict__ s_out,
             const float* __restrict__ s_fr,
             float* __restrict__ out,
             int batch, float idf)
{
    const int p = blockIdx.x * blockDim.x + threadIdx.x;
    if (p >= batch) return;

    int2 pe = g_pairs[p];
    const int d = pe.x;
    const int e = pe.y;

    long long row = (long long)d * (long long)N_FEAT;
    float dl  = __ldg(gf + row + COL_DOCLEN);
    float tf  = __ldg(gf + row + COL_TF);
    float inl = __ldg(gf + row + COL_INLINK);
    float2 op = __ldg(reinterpret_cast<const float2*>(gf + row + COL_OUTLINK));
    float oul = op.x, pr = op.y;

    uint32_t bits = threefry_bits((uint32_t)e);
    float u = __uint_as_float((bits >> 9) | 0x3f800000u) - 1.0f;
    u = fmaxf(0.0f, u);

    const float k1  = __ldg(s_k1);
    const float b   = __ldg(s_b);
    const float bw  = __ldg(s_bw);
    const float prw = __ldg(s_pr);
    const float inw = __ldg(s_in);
    const float otw = __ldg(s_out);
    const float frw = __ldg(s_fr);
    const float avg = g_avg;

    float num  = tf * (k1 + 1.0f);
    float den  = tf + k1 * (1.0f - b + b * (dl / avg));
    float bm25 = idf * (num / den);
    float pg   = prw * pr + inw * inl + otw * oul;
    out[e] = bw * bm25 + pg + u * frw;
}

// ---------------------------------------------------------------------------
extern "C" void kernel_launch(void* const* d_in, const int* in_sizes, int n_in,
                              void* d_out, int out_size)
{
    const int*   idxs = (const int*)d_in[0];
    const float* gf   = (const float*)d_in[1];
    const float* k1   = (const float*)d_in[2];
    const float* b    = (const float*)d_in[3];
    const float* bw   = (const float*)d_in[4];
    const float* prw  = (const float*)d_in[5];
    const float* inw  = (const float*)d_in[6];
    const float* outw = (const float*)d_in[7];
    const float* frw  = (const float*)d_in[8];
    float* out = (float*)d_out;

    int batch  = in_sizes[0];
    int n_docs = in_sizes[1] / N_FEAT;

    // idf in the reference's exact f32 operation order (num == total):
    float total = (float)n_docs;
    float idf = logf(((total - total) + 0.5f) / (total + 0.5f) + 1.0f);

    zero_hist_kernel<<<NB / TPB, TPB>>>();
    col16_hist_kernel<<<SUM_BLOCKS, TPB>>>(gf, idxs, n_docs, batch);
    finalize_scan_kernel<<<1, SCAN_TPB>>>(n_docs);
    scatter_kernel<<<SUM_BLOCKS, TPB>>>(idxs, batch);
    final_kernel<<<(batch + TPB - 1) / TPB, TPB>>>(gf, k1, b, bw, prw, inw,
                                                   outw, frw, out, batch, idf);
}

// round 6
// speedup vs baseline: 2.3445x; 2.3445x over previous
#include <cuda_runtime.h>
#include <cstdint>
#include <cmath>

// ---------------------------------------------------------------------------
// WeightedRankNet, L2-resident packed-table strategy:
//   1) sweep: sequentially pack (dl, tf, inl, oul, pr) -> 32B/doc table
//      (32 MB, fits L2) + col16 partial sums. Table reads use __ldcs
//      (evict-first) so packed writes stay L2-resident.
//   2) finalize: fold partials -> g_avg
//   3) gather: one 32B L2-resident slot per element + threefry + score
// Threefry-2x32-20, key=(0,1), partitionable: bits = out0 ^ out1.
// ---------------------------------------------------------------------------

#define N_FEAT        136
#define COL_DOCLEN    14
#define COL_WHOLE_LEN 16
#define COL_TF        24
#define COL_INLINK    127
#define COL_OUTLINK   128
#define COL_PAGERANK  129

#define TPB        256
#define SUM_BLOCKS 1024
#define MAX_DOCS   (1 << 20)

struct __align__(32) PackedDoc {
    float4 a;   // dl, tf, inl, oul
    float4 b;   // pr, -, -, -
};

__device__ PackedDoc g_packed[MAX_DOCS];   // 32 MB
__device__ float     g_partials[SUM_BLOCKS];
__device__ float     g_avg;

// ---- 1) pack sweep + col16 partial sums -------------------------------------
__global__ void __launch_bounds__(TPB)
sweep_kernel(const float* __restrict__ gf, int n_docs)
{
    const int tid      = blockIdx.x * blockDim.x + threadIdx.x;
    const int nthreads = gridDim.x * blockDim.x;

    float csum = 0.0f;
    for (int i = tid; i < n_docs; i += nthreads) {
        const float* row = gf + (long long)i * N_FEAT;
        // streaming loads (evict-first): don't pollute L2, packed writes stay
        float dl  = __ldcs(row + COL_DOCLEN);
        float c16 = __ldcs(row + COL_WHOLE_LEN);
        float tf  = __ldcs(row + COL_TF);
        float inl = __ldcs(row + COL_INLINK);
        float2 op = __ldcs(reinterpret_cast<const float2*>(row + COL_OUTLINK));

        csum += c16;

        PackedDoc p;
        p.a = make_float4(dl, tf, inl, op.x);
        p.b = make_float4(op.y, 0.0f, 0.0f, 0.0f);
        g_packed[i] = p;
    }

    __shared__ float sd[TPB];
    sd[threadIdx.x] = csum;
    __syncthreads();
    for (int k = TPB / 2; k > 0; k >>= 1) {
        if (threadIdx.x < k) sd[threadIdx.x] += sd[threadIdx.x + k];
        __syncthreads();
    }
    if (threadIdx.x == 0) g_partials[blockIdx.x] = sd[0];
}

// ---- 2) finalize: fold partials into the mean --------------------------------
__global__ void finalize_avg_kernel(int n_docs) {
    __shared__ float sd[SUM_BLOCKS];
    sd[threadIdx.x] = g_partials[threadIdx.x];
    __syncthreads();
    for (int k = SUM_BLOCKS / 2; k > 0; k >>= 1) {
        if (threadIdx.x < k) sd[threadIdx.x] += sd[threadIdx.x + k];
        __syncthreads();
    }
    if (threadIdx.x == 0) g_avg = sd[0] / (float)n_docs;
}

// ---- Threefry-2x32 -------------------------------------------------------------
__device__ __forceinline__ uint32_t rotl32(uint32_t x, uint32_t r) {
    return __funnelshift_l(x, x, r);
}

__device__ __forceinline__ uint32_t threefry_bits(uint32_t ctr) {
    uint32_t x0 = 0u;
    uint32_t x1 = ctr;
    const uint32_t ks0 = 0u, ks1 = 1u, ks2 = 0x1BD11BDBu;
    x0 += ks0; x1 += ks1;
#define TF_R(r) { x0 += x1; x1 = rotl32(x1, (r)); x1 ^= x0; }
    TF_R(13) TF_R(15) TF_R(26) TF_R(6)
    x0 += ks1; x1 += ks2 + 1u;
    TF_R(17) TF_R(29) TF_R(16) TF_R(24)
    x0 += ks2; x1 += ks0 + 2u;
    TF_R(13) TF_R(15) TF_R(26) TF_R(6)
    x0 += ks0; x1 += ks1 + 3u;
    TF_R(17) TF_R(29) TF_R(16) TF_R(24)
    x0 += ks1; x1 += ks2 + 4u;
    TF_R(13) TF_R(15) TF_R(26) TF_R(6)
    x0 += ks2; x1 += ks0 + 5u;
#undef TF_R
    return x0 ^ x1;
}

// ---- 3) gather from L2-resident packed table ----------------------------------
__global__ void __launch_bounds__(TPB)
gather_kernel(const int* __restrict__ idxs,
              const float* __restrict__ s_k1,
              const float* __restrict__ s_b,
              const float* __restrict__ s_bw,
              const float* __restrict__ s_pr,
              const float* __restrict__ s_in,
              const float* __restrict__ s_out,
              const float* __restrict__ s_fr,
              float* __restrict__ out,
              int batch, float idf)
{
    const int tid  = blockIdx.x * blockDim.x + threadIdx.x;
    const int base = tid * 4;
    if (base >= batch) return;

    int idx[4];
    if (base + 3 < batch) {
        int4 iv = *reinterpret_cast<const int4*>(idxs + base);
        idx[0] = iv.x; idx[1] = iv.y; idx[2] = iv.z; idx[3] = iv.w;
    } else {
        #pragma unroll
        for (int k = 0; k < 4; k++)
            idx[k] = (base + k < batch) ? idxs[base + k] : 0;
    }

    float4 a[4];
    float  pr[4];
    #pragma unroll
    for (int k = 0; k < 4; k++) {
        const PackedDoc* p = &g_packed[idx[k]];
        a[k]  = __ldg(&p->a);
        pr[k] = __ldg(&p->b.x);
    }

    const float k1  = __ldg(s_k1);
    const float b   = __ldg(s_b);
    const float bw  = __ldg(s_bw);
    const float prw = __ldg(s_pr);
    const float inw = __ldg(s_in);
    const float otw = __ldg(s_out);
    const float frw = __ldg(s_fr);
    const float avg = g_avg;

    float res[4];
    #pragma unroll
    for (int k = 0; k < 4; k++) {
        float dl  = a[k].x, tf = a[k].y, inl = a[k].z, oul = a[k].w;
        uint32_t bits = threefry_bits((uint32_t)(base + k));
        float u = __uint_as_float((bits >> 9) | 0x3f800000u) - 1.0f;
        u = fmaxf(0.0f, u);
        float num  = tf * (k1 + 1.0f);
        float den  = tf + k1 * (1.0f - b + b * (dl / avg));
        float bm25 = idf * (num / den);
        float pg   = prw * pr[k] + inw * inl + otw * oul;
        res[k] = bw * bm25 + pg + u * frw;
    }

    if (base + 3 < batch) {
        *reinterpret_cast<float4*>(out + base) =
            make_float4(res[0], res[1], res[2], res[3]);
    } else {
        #pragma unroll
        for (int k = 0; k < 4; k++)
            if (base + k < batch) out[base + k] = res[k];
    }
}

// ---------------------------------------------------------------------------
extern "C" void kernel_launch(void* const* d_in, const int* in_sizes, int n_in,
                              void* d_out, int out_size)
{
    const int*   idxs = (const int*)d_in[0];
    const float* gf   = (const float*)d_in[1];
    const float* k1   = (const float*)d_in[2];
    const float* b    = (const float*)d_in[3];
    const float* bw   = (const float*)d_in[4];
    const float* prw  = (const float*)d_in[5];
    const float* inw  = (const float*)d_in[6];
    const float* outw = (const float*)d_in[7];
    const float* frw  = (const float*)d_in[8];
    float* out = (float*)d_out;

    int batch  = in_sizes[0];
    int n_docs = in_sizes[1] / N_FEAT;
    if (n_docs > MAX_DOCS) n_docs = MAX_DOCS;

    // idf in the reference's exact f32 operation order (num == total):
    float total = (float)n_docs;
    float idf = logf(((total - total) + 0.5f) / (total + 0.5f) + 1.0f);

    sweep_kernel<<<SUM_BLOCKS, TPB>>>(gf, n_docs);
    finalize_avg_kernel<<<1, SUM_BLOCKS>>>(n_docs);

    int gblocks = (batch + TPB * 4 - 1) / (TPB * 4);
    gather_kernel<<<gblocks, TPB>>>(idxs, k1, b, bw, prw, inw, outw, frw,
                                    out, batch, idf);
}

// round 7
// speedup vs baseline: 2.3754x; 1.0132x over previous
#include <cuda_runtime.h>
#include <cstdint>
#include <cmath>

// ---------------------------------------------------------------------------
// WeightedRankNet, L2-resident packed-table strategy (R7):
//   1) sweep: 4 rows/thread, all 24 loads batched (MLP up) -> pack
//      (dl, tf, inl, oul, pr) into a 32B/doc table (fits L2) + col16 partials
//   2) gather: each block folds the 1024 partials itself (deterministic),
//      then reads one 32B L2-resident slot per element + threefry + score
// Threefry-2x32-20, key=(0,1), partitionable: bits = out0 ^ out1.
// ---------------------------------------------------------------------------

#define N_FEAT        136
#define COL_DOCLEN    14
#define COL_WHOLE_LEN 16
#define COL_TF        24
#define COL_INLINK    127
#define COL_OUTLINK   128
#define COL_PAGERANK  129

#define TPB        256
#define SUM_BLOCKS 1024
#define MAX_DOCS   (1 << 20)

struct __align__(32) PackedDoc {
    float4 a;   // dl, tf, inl, oul
    float4 b;   // pr, -, -, -
};

__device__ PackedDoc g_packed[MAX_DOCS];   // 32 MB
__device__ float     g_partials[SUM_BLOCKS];

// ---- 1) pack sweep + col16 partial sums (4 rows/thread, batched loads) -------
__global__ void __launch_bounds__(TPB)
sweep_kernel(const float* __restrict__ gf, int n_docs)
{
    const int tid      = blockIdx.x * blockDim.x + threadIdx.x;
    const int S        = gridDim.x * blockDim.x;
    const int step     = 4 * S;

    float csum = 0.0f;

    for (int base = tid; base < n_docs; base += step) {
        int  r[4];
        bool v[4];
        #pragma unroll
        for (int k = 0; k < 4; k++) {
            int rr = base + k * S;
            v[k] = (rr < n_docs);
            r[k] = v[k] ? rr : (n_docs - 1);   // clamp: safe dummy row
        }

        // ---- issue ALL loads back-to-back: 24 outstanding ----
        float dl[4], c16[4], tf[4], inl[4];
        float2 op[4];
        #pragma unroll
        for (int k = 0; k < 4; k++) {
            const float* row = gf + (long long)r[k] * N_FEAT;
            dl[k]  = __ldcs(row + COL_DOCLEN);
            c16[k] = __ldcs(row + COL_WHOLE_LEN);
            tf[k]  = __ldcs(row + COL_TF);
            inl[k] = __ldcs(row + COL_INLINK);
            op[k]  = __ldcs(reinterpret_cast<const float2*>(row + COL_OUTLINK));
        }

        #pragma unroll
        for (int k = 0; k < 4; k++) {
            if (!v[k]) break;
            csum += c16[k];
            PackedDoc p;
            p.a = make_float4(dl[k], tf[k], inl[k], op[k].x);
            p.b = make_float4(op[k].y, 0.0f, 0.0f, 0.0f);
            g_packed[r[k]] = p;
        }
    }

    __shared__ float sd[TPB];
    sd[threadIdx.x] = csum;
    __syncthreads();
    for (int k = TPB / 2; k > 0; k >>= 1) {
        if (threadIdx.x < k) sd[threadIdx.x] += sd[threadIdx.x + k];
        __syncthreads();
    }
    if (threadIdx.x == 0) g_partials[blockIdx.x] = sd[0];
}

// ---- Threefry-2x32 -------------------------------------------------------------
__device__ __forceinline__ uint32_t rotl32(uint32_t x, uint32_t r) {
    return __funnelshift_l(x, x, r);
}

__device__ __forceinline__ uint32_t threefry_bits(uint32_t ctr) {
    uint32_t x0 = 0u;
    uint32_t x1 = ctr;
    const uint32_t ks0 = 0u, ks1 = 1u, ks2 = 0x1BD11BDBu;
    x0 += ks0; x1 += ks1;
#define TF_R(r) { x0 += x1; x1 = rotl32(x1, (r)); x1 ^= x0; }
    TF_R(13) TF_R(15) TF_R(26) TF_R(6)
    x0 += ks1; x1 += ks2 + 1u;
    TF_R(17) TF_R(29) TF_R(16) TF_R(24)
    x0 += ks2; x1 += ks0 + 2u;
    TF_R(13) TF_R(15) TF_R(26) TF_R(6)
    x0 += ks0; x1 += ks1 + 3u;
    TF_R(17) TF_R(29) TF_R(16) TF_R(24)
    x0 += ks1; x1 += ks2 + 4u;
    TF_R(13) TF_R(15) TF_R(26) TF_R(6)
    x0 += ks2; x1 += ks0 + 5u;
#undef TF_R
    return x0 ^ x1;
}

// ---- 2) gather: per-block avg fold + L2-resident packed reads ------------------
__global__ void __launch_bounds__(TPB)
gather_kernel(const int* __restrict__ idxs,
              const float* __restrict__ s_k1,
              const float* __restrict__ s_b,
              const float* __restrict__ s_bw,
              const float* __restrict__ s_pr,
              const float* __restrict__ s_in,
              const float* __restrict__ s_out,
              const float* __restrict__ s_fr,
              float* __restrict__ out,
              int batch, int n_docs, float idf)
{
    const int tid  = blockIdx.x * blockDim.x + threadIdx.x;
    const int base = tid * 4;
    const int t    = threadIdx.x;

    // ---- issue element loads FIRST (overlap with avg fold) ----
    int idx[4];
    bool full = (base + 3 < batch);
    if (full) {
        int4 iv = *reinterpret_cast<const int4*>(idxs + base);
        idx[0] = iv.x; idx[1] = iv.y; idx[2] = iv.z; idx[3] = iv.w;
    } else {
        #pragma unroll
        for (int k = 0; k < 4; k++)
            idx[k] = (base + k < batch) ? idxs[base + (k < batch - base ? k : 0)] : 0;
    }
    if (base >= batch) { idx[0] = idx[1] = idx[2] = idx[3] = 0; }

    float4 a[4];
    float  pr[4];
    #pragma unroll
    for (int k = 0; k < 4; k++) {
        const PackedDoc* p = &g_packed[idx[k]];
        a[k]  = __ldg(&p->a);
        pr[k] = __ldg(&p->b.x);
    }

    // ---- deterministic per-block fold of col16 partials -> avg ----
    __shared__ float sd[TPB];
    {
        float s = g_partials[t] + g_partials[t + 256]
                + g_partials[t + 512] + g_partials[t + 768];
        sd[t] = s;
        __syncthreads();
        for (int k = TPB / 2; k > 0; k >>= 1) {
            if (t < k) sd[t] += sd[t + k];
            __syncthreads();
        }
    }
    const float avg = sd[0] / (float)n_docs;

    if (base >= batch) return;

    const float k1  = __ldg(s_k1);
    const float b   = __ldg(s_b);
    const float bw  = __ldg(s_bw);
    const float prw = __ldg(s_pr);
    const float inw = __ldg(s_in);
    const float otw = __ldg(s_out);
    const float frw = __ldg(s_fr);

    float res[4];
    #pragma unroll
    for (int k = 0; k < 4; k++) {
        float dl  = a[k].x, tf = a[k].y, inl = a[k].z, oul = a[k].w;
        uint32_t bits = threefry_bits((uint32_t)(base + k));
        float u = __uint_as_float((bits >> 9) | 0x3f800000u) - 1.0f;
        u = fmaxf(0.0f, u);
        float num  = tf * (k1 + 1.0f);
        float den  = tf + k1 * (1.0f - b + b * (dl / avg));
        float bm25 = idf * (num / den);
        float pg   = prw * pr[k] + inw * inl + otw * oul;
        res[k] = bw * bm25 + pg + u * frw;
    }

    if (full) {
        *reinterpret_cast<float4*>(out + base) =
            make_float4(res[0], res[1], res[2], res[3]);
    } else {
        #pragma unroll
        for (int k = 0; k < 4; k++)
            if (base + k < batch) out[base + k] = res[k];
    }
}

// ---------------------------------------------------------------------------
extern "C" void kernel_launch(void* const* d_in, const int* in_sizes, int n_in,
                              void* d_out, int out_size)
{
    const int*   idxs = (const int*)d_in[0];
    const float* gf   = (const float*)d_in[1];
    const float* k1   = (const float*)d_in[2];
    const float* b    = (const float*)d_in[3];
    const float* bw   = (const float*)d_in[4];
    const float* prw  = (const float*)d_in[5];
    const float* inw  = (const float*)d_in[6];
    const float* outw = (const float*)d_in[7];
    const float* frw  = (const float*)d_in[8];
    float* out = (float*)d_out;

    int batch  = in_sizes[0];
    int n_docs = in_sizes[1] / N_FEAT;
    if (n_docs > MAX_DOCS) n_docs = MAX_DOCS;

    // idf in the reference's exact f32 operation order (num == total):
    float total = (float)n_docs;
    float idf = logf(((total - total) + 0.5f) / (total + 0.5f) + 1.0f);

    sweep_kernel<<<SUM_BLOCKS, TPB>>>(gf, n_docs);

    int gblocks = (batch + TPB * 4 - 1) / (TPB * 4);
    gather_kernel<<<gblocks, TPB>>>(idxs, k1, b, bw, prw, inw, outw, frw,
                                    out, batch, n_docs, idf);
}

// round 8
// speedup vs baseline: 2.5223x; 1.0619x over previous
#include <cuda_runtime.h>
#include <cstdint>
#include <cmath>

// ---------------------------------------------------------------------------
// WeightedRankNet R8: sweep precomputes per-doc scores into a 16B/doc float4
// table (L2-resident): (A, D, E, PG) where
//   A  = bw*idf*tf*(k1+1),  D = tf + k1*(1-b),  E = k1*b*dl,
//   PG = prw*pr + inw*inl + otw*oul.
// Gather: one float4 L2 load per element + threefry + combine:
//   out = PG + A/(D + E/avg) + u*frw
// avg folded deterministically per gather block from sweep partials.
// Threefry-2x32-20, key=(0,1), partitionable: bits = out0 ^ out1.
// ---------------------------------------------------------------------------

#define N_FEAT        136
#define COL_DOCLEN    14
#define COL_WHOLE_LEN 16
#define COL_TF        24
#define COL_INLINK    127
#define COL_OUTLINK   128
#define COL_PAGERANK  129

#define TPB        256
#define SUM_BLOCKS 1024
#define MAX_DOCS   (1 << 20)

__device__ float4 g_packed[MAX_DOCS];      // 16 MB: (A, D, E, PG)
__device__ float  g_partials[SUM_BLOCKS];

// ---- 1) sweep: pack per-doc partial scores + col16 partial sums ---------------
__global__ void __launch_bounds__(TPB)
sweep_kernel(const float* __restrict__ gf,
             const float* __restrict__ s_k1,
             const float* __restrict__ s_b,
             const float* __restrict__ s_bw,
             const float* __restrict__ s_pr,
             const float* __restrict__ s_in,
             const float* __restrict__ s_out,
             int n_docs, float idf)
{
    const int tid  = blockIdx.x * blockDim.x + threadIdx.x;
    const int S    = gridDim.x * blockDim.x;
    const int step = 4 * S;

    const float k1  = __ldg(s_k1);
    const float b   = __ldg(s_b);
    const float bw  = __ldg(s_bw);
    const float prw = __ldg(s_pr);
    const float inw = __ldg(s_in);
    const float otw = __ldg(s_out);

    const float cA = bw * idf * (k1 + 1.0f);   // A = cA * tf
    const float cD = k1 * (1.0f - b);          // D = tf + cD
    const float cE = k1 * b;                   // E = cE * dl

    float csum = 0.0f;

    for (int base = tid; base < n_docs; base += step) {
        int  r[4];
        bool v[4];
        #pragma unroll
        for (int k = 0; k < 4; k++) {
            int rr = base + k * S;
            v[k] = (rr < n_docs);
            r[k] = v[k] ? rr : (n_docs - 1);
        }

        // issue all 24 loads back-to-back
        float dl[4], c16[4], tf[4], inl[4];
        float2 op[4];
        #pragma unroll
        for (int k = 0; k < 4; k++) {
            const float* row = gf + (long long)r[k] * N_FEAT;
            dl[k]  = __ldcs(row + COL_DOCLEN);
            c16[k] = __ldcs(row + COL_WHOLE_LEN);
            tf[k]  = __ldcs(row + COL_TF);
            inl[k] = __ldcs(row + COL_INLINK);
            op[k]  = __ldcs(reinterpret_cast<const float2*>(row + COL_OUTLINK));
        }

        #pragma unroll
        for (int k = 0; k < 4; k++) {
            if (!v[k]) break;
            csum += c16[k];
            float A  = cA * tf[k];
            float D  = tf[k] + cD;
            float E  = cE * dl[k];
            float PG = prw * op[k].y + inw * inl[k] + otw * op[k].x;
            g_packed[r[k]] = make_float4(A, D, E, PG);
        }
    }

    __shared__ float sd[TPB];
    sd[threadIdx.x] = csum;
    __syncthreads();
    for (int k = TPB / 2; k > 0; k >>= 1) {
        if (threadIdx.x < k) sd[threadIdx.x] += sd[threadIdx.x + k];
        __syncthreads();
    }
    if (threadIdx.x == 0) g_partials[blockIdx.x] = sd[0];
}

// ---- Threefry-2x32 -------------------------------------------------------------
__device__ __forceinline__ uint32_t rotl32(uint32_t x, uint32_t r) {
    return __funnelshift_l(x, x, r);
}

__device__ __forceinline__ uint32_t threefry_bits(uint32_t ctr) {
    uint32_t x0 = 0u;
    uint32_t x1 = ctr;
    const uint32_t ks0 = 0u, ks1 = 1u, ks2 = 0x1BD11BDBu;
    x0 += ks0; x1 += ks1;
#define TF_R(r) { x0 += x1; x1 = rotl32(x1, (r)); x1 ^= x0; }
    TF_R(13) TF_R(15) TF_R(26) TF_R(6)
    x0 += ks1; x1 += ks2 + 1u;
    TF_R(17) TF_R(29) TF_R(16) TF_R(24)
    x0 += ks2; x1 += ks0 + 2u;
    TF_R(13) TF_R(15) TF_R(26) TF_R(6)
    x0 += ks0; x1 += ks1 + 3u;
    TF_R(17) TF_R(29) TF_R(16) TF_R(24)
    x0 += ks1; x1 += ks2 + 4u;
    TF_R(13) TF_R(15) TF_R(26) TF_R(6)
    x0 += ks2; x1 += ks0 + 5u;
#undef TF_R
    return x0 ^ x1;
}

// ---- 2) gather: per-block avg fold + one float4 per element --------------------
__global__ void __launch_bounds__(TPB)
gather_kernel(const int* __restrict__ idxs,
              const float* __restrict__ s_fr,
              float* __restrict__ out,
              int batch, int n_docs)
{
    const int tid  = blockIdx.x * blockDim.x + threadIdx.x;
    const int base = tid * 4;
    const int t    = threadIdx.x;

    // issue element loads first (overlap the avg fold)
    int idx[4];
    const bool full = (base + 3 < batch);
    if (full) {
        int4 iv = *reinterpret_cast<const int4*>(idxs + base);
        idx[0] = iv.x; idx[1] = iv.y; idx[2] = iv.z; idx[3] = iv.w;
    } else if (base < batch) {
        #pragma unroll
        for (int k = 0; k < 4; k++)
            idx[k] = (base + k < batch) ? idxs[base + k] : idxs[base];
    } else {
        idx[0] = idx[1] = idx[2] = idx[3] = 0;
    }

    float4 p[4];
    #pragma unroll
    for (int k = 0; k < 4; k++)
        p[k] = __ldg(&g_packed[idx[k]]);

    // deterministic per-block fold of col16 partials -> avg
    __shared__ float sd[TPB];
    {
        float s = g_partials[t] + g_partials[t + 256]
                + g_partials[t + 512] + g_partials[t + 768];
        sd[t] = s;
        __syncthreads();
        for (int k = TPB / 2; k > 0; k >>= 1) {
            if (t < k) sd[t] += sd[t + k];
            __syncthreads();
        }
    }
    const float inv_avg = (float)n_docs / sd[0];   // 1/avg

    if (base >= batch) return;

    const float frw = __ldg(s_fr);

    float res[4];
    #pragma unroll
    for (int k = 0; k < 4; k++) {
        uint32_t bits = threefry_bits((uint32_t)(base + k));
        float u = __uint_as_float((bits >> 9) | 0x3f800000u) - 1.0f;
        u = fmaxf(0.0f, u);
        // out = PG + A/(D + E/avg) + u*frw
        res[k] = p[k].w + p[k].x / (p[k].y + p[k].z * inv_avg) + u * frw;
    }

    if (full) {
        *reinterpret_cast<float4*>(out + base) =
            make_float4(res[0], res[1], res[2], res[3]);
    } else {
        #pragma unroll
        for (int k = 0; k < 4; k++)
            if (base + k < batch) out[base + k] = res[k];
    }
}

// ---------------------------------------------------------------------------
extern "C" void kernel_launch(void* const* d_in, const int* in_sizes, int n_in,
                              void* d_out, int out_size)
{
    const int*   idxs = (const int*)d_in[0];
    const float* gf   = (const float*)d_in[1];
    const float* k1   = (const float*)d_in[2];
    const float* b    = (const float*)d_in[3];
    const float* bw   = (const float*)d_in[4];
    const float* prw  = (const float*)d_in[5];
    const float* inw  = (const float*)d_in[6];
    const float* outw = (const float*)d_in[7];
    const float* frw  = (const float*)d_in[8];
    float* out = (float*)d_out;

    int batch  = in_sizes[0];
    int n_docs = in_sizes[1] / N_FEAT;
    if (n_docs > MAX_DOCS) n_docs = MAX_DOCS;

    // idf in the reference's exact f32 operation order (num == total):
    float total = (float)n_docs;
    float idf = logf(((total - total) + 0.5f) / (total + 0.5f) + 1.0f);

    sweep_kernel<<<SUM_BLOCKS, TPB>>>(gf, k1, b, bw, prw, inw, outw,
                                      n_docs, idf);

    int gblocks = (batch + TPB * 4 - 1) / (TPB * 4);
    gather_kernel<<<gblocks, TPB>>>(idxs, frw, out, batch, n_docs);
}